// round 2
// baseline (speedup 1.0000x reference)
#include <cuda_runtime.h>
#include <cstdint>

#define B_WIN   2048
#define NTOK    64
#define DIM     256
#define NHEADS  8
#define HDIM    32
#define QKVDIM  768
#define MROWS   (B_WIN * NTOK)          // 131072
#define SCALE   0.17677669529663687f    // 32^-0.5

// ---------------- scratch (device globals; no cudaMalloc allowed) ----------
// g_qkv layout: [s][b*8+h][n*32+d], plane stride = 2048*8*64*32
#define QKV_PLANE (2048ull * 8ull * 64ull * 32ull)
__device__ float g_qkv[3ull * QKV_PLANE];
__device__ float g_ao[(size_t)MROWS * DIM];

// ---------------- GEMM: C[M x NC] = A[M x K] * W[NC x K]^T + bias ----------
// 64x64 block tile, BK=16, 256 threads, 4x4 per-thread microtile.
// MODE 0: scatter into g_qkv (q scaled). MODE 1: plain write to `out`.
template <int MODE>
__global__ void __launch_bounds__(256)
gemm_kernel(const float* __restrict__ A,
            const float* __restrict__ W,
            const float* __restrict__ bias,
            float* __restrict__ out,
            int K)
{
    // row stride 68 floats = 272 bytes: 16B-aligned so LDS.128 is legal.
    __shared__ float As[16][68];   // [k][m]
    __shared__ float Bs[16][68];   // [k][n]

    const int tid  = threadIdx.x;
    const int row0 = blockIdx.y * 64;
    const int col0 = blockIdx.x * 64;
    const int tx   = tid & 15;     // row group
    const int ty   = tid >> 4;     // col group

    float acc[4][4];
#pragma unroll
    for (int i = 0; i < 4; i++)
#pragma unroll
        for (int j = 0; j < 4; j++) acc[i][j] = 0.f;

    const int lr = tid >> 2;            // 0..63 load row
    const int lc = (tid & 3) * 4;       // 0,4,8,12 load col (k)

    for (int k0 = 0; k0 < K; k0 += 16) {
        // A tile: rows row0..row0+63, k k0..k0+15, transposed into As[k][m]
        {
            float4 v = *(const float4*)(A + (size_t)(row0 + lr) * K + k0 + lc);
            As[lc + 0][lr] = v.x; As[lc + 1][lr] = v.y;
            As[lc + 2][lr] = v.z; As[lc + 3][lr] = v.w;
        }
        // W tile: W[col0+n][k0+k] -> Bs[k][n]
        {
            float4 v = *(const float4*)(W + (size_t)(col0 + lr) * K + k0 + lc);
            Bs[lc + 0][lr] = v.x; Bs[lc + 1][lr] = v.y;
            Bs[lc + 2][lr] = v.z; Bs[lc + 3][lr] = v.w;
        }
        __syncthreads();
#pragma unroll
        for (int kk = 0; kk < 16; kk++) {
            float a[4], b[4];
            *(float4*)a = *(const float4*)&As[kk][tx * 4];
            *(float4*)b = *(const float4*)&Bs[kk][ty * 4];
#pragma unroll
            for (int i = 0; i < 4; i++)
#pragma unroll
                for (int j = 0; j < 4; j++)
                    acc[i][j] += a[i] * b[j];
        }
        __syncthreads();
    }

#pragma unroll
    for (int i = 0; i < 4; i++) {
        const int r = row0 + tx * 4 + i;
#pragma unroll
        for (int j = 0; j < 4; j++) {
            const int c = col0 + ty * 4 + j;
            float v = acc[i][j] + bias[c];
            if (MODE == 0) {
                const int s = c >> 8;
                const int h = (c >> 5) & 7;
                const int d = c & 31;
                if (s == 0) v *= SCALE;
                const int b = r >> 6;
                const int n = r & 63;
                g_qkv[(size_t)s * QKV_PLANE
                      + ((size_t)(b * 8 + h)) * 2048
                      + n * 32 + d] = v;
            } else {
                out[(size_t)r * DIM + c] = v;
            }
        }
    }
}

// ---------------- attention per (window, head) ------------------------------
__global__ void __launch_bounds__(256)
attn_kernel(const float* __restrict__ mask,
            const float* __restrict__ bias_table)
{
    const int bh = blockIdx.x;          // b*8 + h
    const int b  = bh >> 3;
    const int h  = bh & 7;

    __shared__ float qs[64][32];        // [i][d]
    __shared__ float kst[32][64];       // [d][j]  (K transposed)
    __shared__ float vs[64][32];        // [j][d]
    __shared__ float ps[64][68];        // probabilities, padded (68*4=272B, 16B aligned)
    __shared__ float bt[225];           // bias_table column for this head

    const int tid  = threadIdx.x;
    const int warp = tid >> 5;
    const int lane = tid & 31;

    const float* Qp = g_qkv + (size_t)bh * 2048;
    const float* Kp = g_qkv + QKV_PLANE + (size_t)bh * 2048;
    const float* Vp = g_qkv + 2 * QKV_PLANE + (size_t)bh * 2048;

    // loads: 512 float4 per tensor, 256 threads
    for (int f = tid; f < 512; f += 256) {
        ((float4*)qs)[f] = ((const float4*)Qp)[f];
        ((float4*)vs)[f] = ((const float4*)Vp)[f];
        float4 kv = ((const float4*)Kp)[f];
        const int j = f >> 3;
        const int d = (f & 7) * 4;
        kst[d + 0][j] = kv.x; kst[d + 1][j] = kv.y;
        kst[d + 2][j] = kv.z; kst[d + 3][j] = kv.w;
    }
    if (tid < 225) bt[tid] = bias_table[tid * NHEADS + h];
    __syncthreads();

    const float* mrow = mask + (size_t)b * 4096;

    // each warp owns rows warp*8 .. warp*8+7; lane covers cols (lane, lane+32)
    const int yj0 = lane >> 3,        xj0 = lane & 7;
    const int yj1 = (lane + 32) >> 3, xj1 = (lane + 32) & 7;

#pragma unroll 1
    for (int r = 0; r < 8; r++) {
        const int i  = warp * 8 + r;
        const int yi = i >> 3, xi = i & 7;

        float acc0 = 0.f, acc1 = 0.f;
#pragma unroll
        for (int d4 = 0; d4 < 32; d4 += 4) {
            float4 qv = *(const float4*)&qs[i][d4];
            acc0 += qv.x * kst[d4 + 0][lane] + qv.y * kst[d4 + 1][lane]
                  + qv.z * kst[d4 + 2][lane] + qv.w * kst[d4 + 3][lane];
            acc1 += qv.x * kst[d4 + 0][lane + 32] + qv.y * kst[d4 + 1][lane + 32]
                  + qv.z * kst[d4 + 2][lane + 32] + qv.w * kst[d4 + 3][lane + 32];
        }
        const int idx0 = (yi - yj0 + 7) * 15 + (xi - xj0 + 7);
        const int idx1 = (yi - yj1 + 7) * 15 + (xi - xj1 + 7);
        float s0 = acc0 + bt[idx0] + mrow[i * 64 + lane];
        float s1 = acc1 + bt[idx1] + mrow[i * 64 + lane + 32];

        // softmax over 64 values held 2-per-lane
        float m = fmaxf(s0, s1);
#pragma unroll
        for (int o = 16; o > 0; o >>= 1)
            m = fmaxf(m, __shfl_xor_sync(0xffffffffu, m, o));
        float e0 = __expf(s0 - m);
        float e1 = __expf(s1 - m);
        float sum = e0 + e1;
#pragma unroll
        for (int o = 16; o > 0; o >>= 1)
            sum += __shfl_xor_sync(0xffffffffu, sum, o);
        const float inv = 1.f / sum;
        ps[i][lane]      = e0 * inv;
        ps[i][lane + 32] = e1 * inv;
    }
    // no __syncthreads needed: each warp consumes only the ps rows it produced,
    // and vs was synced after the initial load.

#pragma unroll 1
    for (int r = 0; r < 8; r++) {
        const int i = warp * 8 + r;
        float acc = 0.f;
#pragma unroll
        for (int j = 0; j < 64; j += 4) {
            float4 p = *(const float4*)&ps[i][j];
            acc += p.x * vs[j + 0][lane] + p.y * vs[j + 1][lane]
                 + p.z * vs[j + 2][lane] + p.w * vs[j + 3][lane];
        }
        g_ao[((size_t)b * 64 + i) * DIM + h * 32 + lane] = acc;
    }
}

// ---------------- launch ----------------------------------------------------
extern "C" void kernel_launch(void* const* d_in, const int* in_sizes, int n_in,
                              void* d_out, int out_size)
{
    const float* x          = (const float*)d_in[0]; // (2048,64,256)
    const float* mask       = (const float*)d_in[1]; // (2048,1,64,64)
    const float* w_qkv      = (const float*)d_in[2]; // (768,256)
    const float* b_qkv      = (const float*)d_in[3]; // (768)
    const float* w_proj     = (const float*)d_in[4]; // (256,256)
    const float* b_proj     = (const float*)d_in[5]; // (256)
    const float* bias_table = (const float*)d_in[6]; // (225,8)
    float* out = (float*)d_out;                      // (2048,64,256)

    (void)in_sizes; (void)n_in; (void)out_size;

    float* ao_ptr = nullptr;
    cudaGetSymbolAddress((void**)&ao_ptr, g_ao);

    // 1) QKV GEMM + bias, scattered into g_qkv with q pre-scaled
    {
        dim3 grid(QKVDIM / 64, MROWS / 64);   // 12 x 2048
        gemm_kernel<0><<<grid, 256>>>(x, w_qkv, b_qkv, nullptr, DIM);
    }
    // 2) windowed attention per (b, h)
    {
        attn_kernel<<<B_WIN * NHEADS, 256>>>(mask, bias_table);
    }
    // 3) output projection
    {
        dim3 grid(DIM / 64, MROWS / 64);      // 4 x 2048
        gemm_kernel<1><<<grid, 256>>>(ao_ptr, w_proj, b_proj, out, DIM);
    }
}

// round 4
// speedup vs baseline: 2.0510x; 2.0510x over previous
#include <cuda_runtime.h>
#include <cuda_bf16.h>
#include <cstdint>

#define B_WIN   2048
#define NTOK    64
#define DIM     256
#define NHEADS  8
#define QKVDIM  768
#define MROWS   (B_WIN * NTOK)          // 131072
#define SCALE   0.17677669529663687f    // 32^-0.5

// ---------------- scratch (device globals; no cudaMalloc allowed) ----------
#define QKV_PLANE (2048ull * 8ull * 64ull * 32ull)
__device__ float g_qkv[3ull * QKV_PLANE];                       // fp32 q/k/v
__device__ __nv_bfloat16 g_x_hi[(size_t)MROWS * DIM];
__device__ __nv_bfloat16 g_x_lo[(size_t)MROWS * DIM];
__device__ __nv_bfloat16 g_ao_hi[(size_t)MROWS * DIM];
__device__ __nv_bfloat16 g_ao_lo[(size_t)MROWS * DIM];
__device__ __nv_bfloat16 g_wq_hi[QKVDIM * DIM];
__device__ __nv_bfloat16 g_wq_lo[QKVDIM * DIM];
__device__ __nv_bfloat16 g_wp_hi[DIM * DIM];
__device__ __nv_bfloat16 g_wp_lo[DIM * DIM];

// ================= helpers ==================================================
__device__ __forceinline__ uint32_t smem_u32(const void* p) {
    uint32_t a;
    asm("{ .reg .u64 t; cvta.to.shared.u64 t, %1; cvt.u32.u64 %0, t; }"
        : "=r"(a) : "l"(p));
    return a;
}

__device__ __forceinline__ void ldsm_x4(uint32_t* r, uint32_t addr) {
    asm volatile("ldmatrix.sync.aligned.m8n8.x4.shared.b16 {%0,%1,%2,%3}, [%4];"
                 : "=r"(r[0]), "=r"(r[1]), "=r"(r[2]), "=r"(r[3]) : "r"(addr));
}

// D += A(bf16 16x16) * B(bf16 16x8), fp32 accumulate
__device__ __forceinline__ void mma16816(float* c, const uint32_t* a, const uint32_t* b) {
    asm volatile("mma.sync.aligned.m16n8k16.row.col.f32.bf16.bf16.f32 "
                 "{%0,%1,%2,%3}, {%4,%5,%6,%7}, {%8,%9}, {%0,%1,%2,%3};"
                 : "+f"(c[0]), "+f"(c[1]), "+f"(c[2]), "+f"(c[3])
                 : "r"(a[0]), "r"(a[1]), "r"(a[2]), "r"(a[3]),
                   "r"(b[0]), "r"(b[1]));
}

// ================= fp32 -> (hi, lo) bf16 split =============================
__global__ void convert_split(const float* __restrict__ src,
                              __nv_bfloat16* __restrict__ hi,
                              __nv_bfloat16* __restrict__ lo, int n4)
{
    int i = blockIdx.x * blockDim.x + threadIdx.x;
    if (i >= n4) return;
    float4 v = ((const float4*)src)[i];
    float f[4] = {v.x, v.y, v.z, v.w};
    __nv_bfloat16 h[4], l[4];
#pragma unroll
    for (int k = 0; k < 4; k++) {
        h[k] = __float2bfloat16(f[k]);
        l[k] = __float2bfloat16(f[k] - __bfloat162float(h[k]));
    }
    ((__nv_bfloat162*)hi)[2*i]   = __halves2bfloat162(h[0], h[1]);
    ((__nv_bfloat162*)hi)[2*i+1] = __halves2bfloat162(h[2], h[3]);
    ((__nv_bfloat162*)lo)[2*i]   = __halves2bfloat162(l[0], l[1]);
    ((__nv_bfloat162*)lo)[2*i+1] = __halves2bfloat162(l[2], l[3]);
}

// ================= HMMA GEMM ================================================
// C[128 x 64] block tile = A[128 x 256] * W[64 x 256]^T  (3-term bf16 split)
// 8 warps: 4(M) x 2(N), warp tile 32x32 via mma.m16n8k16.
// MODE 0: epilogue scatters into g_qkv (q scaled). MODE 1: writes `out`.

#define SSTR  72                    // bf16 per smem row (144B = 9*16B, conflict-free)
#define OFF_AH 0
#define OFF_AL 18432
#define OFF_BH 36864
#define OFF_BL 46080
#define GEMM_SMEM 55296

template <int MODE>
__global__ void __launch_bounds__(256)
gemm_mma(const __nv_bfloat16* __restrict__ Ah, const __nv_bfloat16* __restrict__ Al,
         const __nv_bfloat16* __restrict__ Wh, const __nv_bfloat16* __restrict__ Wl,
         const float* __restrict__ bias, float* __restrict__ out)
{
    extern __shared__ char smem[];
    __nv_bfloat16* sAh = (__nv_bfloat16*)(smem + OFF_AH);
    __nv_bfloat16* sAl = (__nv_bfloat16*)(smem + OFF_AL);
    __nv_bfloat16* sBh = (__nv_bfloat16*)(smem + OFF_BH);
    __nv_bfloat16* sBl = (__nv_bfloat16*)(smem + OFF_BL);

    const int tid  = threadIdx.x;
    const int lane = tid & 31;
    const int warp = tid >> 5;
    const int wm   = warp >> 1;          // 0..3
    const int wn   = warp & 1;           // 0..1
    const int row0 = blockIdx.y * 128;
    const int col0 = blockIdx.x * 64;

    float acc[2][4][4];
#pragma unroll
    for (int a = 0; a < 2; a++)
#pragma unroll
        for (int b = 0; b < 4; b++)
#pragma unroll
            for (int c = 0; c < 4; c++) acc[a][b][c] = 0.f;

    // ldmatrix lane addresses (element offsets within smem planes)
    const int a_row = wm * 32 + (lane & 15);
    const int a_ksel = (lane >> 4) * 8;
    const int b_row = wn * 32 + ((lane >> 4) << 3) + (lane & 7);
    const int b_ksel = ((lane >> 3) & 1) << 3;

    for (int kc = 0; kc < 4; kc++) {
        const int k0 = kc * 64;
        __syncthreads();
        // A tile: 128x64, 1024 uint4 chunks per plane, 4 per thread
#pragma unroll
        for (int t = 0; t < 4; t++) {
            const int idx = tid + t * 256;
            const int r = idx >> 3, c8 = (idx & 7) * 8;
            const size_t go = (size_t)(row0 + r) * 256 + k0 + c8;
            *(uint4*)(sAh + r * SSTR + c8) = *(const uint4*)(Ah + go);
            *(uint4*)(sAl + r * SSTR + c8) = *(const uint4*)(Al + go);
        }
        // W tile: 64x64, 512 chunks per plane, 2 per thread
#pragma unroll
        for (int t = 0; t < 2; t++) {
            const int idx = tid + t * 256;
            const int r = idx >> 3, c8 = (idx & 7) * 8;
            const size_t go = (size_t)(col0 + r) * 256 + k0 + c8;
            *(uint4*)(sBh + r * SSTR + c8) = *(const uint4*)(Wh + go);
            *(uint4*)(sBl + r * SSTR + c8) = *(const uint4*)(Wl + go);
        }
        __syncthreads();

#pragma unroll
        for (int kk = 0; kk < 64; kk += 16) {
            uint32_t a_h[2][4], a_l[2][4], b_h[2][4], b_l[2][4];
#pragma unroll
            for (int mt = 0; mt < 2; mt++) {
                const int off = (a_row + mt * 16) * SSTR + kk + a_ksel;
                ldsm_x4(a_h[mt], smem_u32(sAh + off));
                ldsm_x4(a_l[mt], smem_u32(sAl + off));
            }
#pragma unroll
            for (int g = 0; g < 2; g++) {
                const int off = (b_row + g * 16) * SSTR + kk + b_ksel;
                ldsm_x4(b_h[g], smem_u32(sBh + off));
                ldsm_x4(b_l[g], smem_u32(sBl + off));
            }
#pragma unroll
            for (int mt = 0; mt < 2; mt++)
#pragma unroll
                for (int g = 0; g < 2; g++)
#pragma unroll
                    for (int j = 0; j < 2; j++) {
                        float* c = acc[mt][g * 2 + j];
                        mma16816(c, a_h[mt], &b_h[g][j * 2]);
                        mma16816(c, a_h[mt], &b_l[g][j * 2]);
                        mma16816(c, a_l[mt], &b_h[g][j * 2]);
                    }
        }
    }

    // epilogue
    const int gid = lane >> 2, tig = lane & 3;
#pragma unroll
    for (int mt = 0; mt < 2; mt++)
#pragma unroll
        for (int g = 0; g < 2; g++)
#pragma unroll
            for (int j = 0; j < 2; j++) {
                const int nf = g * 2 + j;
                const int col = col0 + wn * 32 + g * 16 + j * 8 + tig * 2;
                const float2 bv = *(const float2*)(bias + col);
#pragma unroll
                for (int rs = 0; rs < 2; rs++) {
                    const int row = row0 + wm * 32 + mt * 16 + gid + rs * 8;
                    float v0 = acc[mt][nf][rs * 2 + 0] + bv.x;
                    float v1 = acc[mt][nf][rs * 2 + 1] + bv.y;
                    if (MODE == 0) {
                        const int s = col >> 8;
                        if (s == 0) { v0 *= SCALE; v1 *= SCALE; }
                        const int h = (col >> 5) & 7, d = col & 31;
                        const int b = row >> 6, n = row & 63;
                        *(float2*)(g_qkv + (size_t)s * QKV_PLANE
                                   + (size_t)(b * 8 + h) * 2048 + n * 32 + d)
                            = make_float2(v0, v1);
                    } else {
                        *(float2*)(out + (size_t)row * 256 + col)
                            = make_float2(v0, v1);
                    }
                }
            }
}

// ---------------- attention per (window, head) — fp32 ----------------------
__global__ void __launch_bounds__(256)
attn_kernel(const float* __restrict__ mask,
            const float* __restrict__ bias_table)
{
    const int bh = blockIdx.x;          // b*8 + h
    const int b  = bh >> 3;
    const int h  = bh & 7;

    __shared__ float qs[64][32];
    __shared__ float kst[32][64];
    __shared__ float vs[64][32];
    __shared__ float ps[64][68];
    __shared__ float bt[225];

    const int tid  = threadIdx.x;
    const int warp = tid >> 5;
    const int lane = tid & 31;

    const float* Qp = g_qkv + (size_t)bh * 2048;
    const float* Kp = g_qkv + QKV_PLANE + (size_t)bh * 2048;
    const float* Vp = g_qkv + 2 * QKV_PLANE + (size_t)bh * 2048;

    for (int f = tid; f < 512; f += 256) {
        ((float4*)qs)[f] = ((const float4*)Qp)[f];
        ((float4*)vs)[f] = ((const float4*)Vp)[f];
        float4 kv = ((const float4*)Kp)[f];
        const int j = f >> 3;
        const int d = (f & 7) * 4;
        kst[d + 0][j] = kv.x; kst[d + 1][j] = kv.y;
        kst[d + 2][j] = kv.z; kst[d + 3][j] = kv.w;
    }
    if (tid < 225) bt[tid] = bias_table[tid * NHEADS + h];
    __syncthreads();

    const float* mrow = mask + (size_t)b * 4096;

    const int yj0 = lane >> 3,        xj0 = lane & 7;
    const int yj1 = (lane + 32) >> 3, xj1 = (lane + 32) & 7;

#pragma unroll 1
    for (int r = 0; r < 8; r++) {
        const int i  = warp * 8 + r;
        const int yi = i >> 3, xi = i & 7;

        float acc0 = 0.f, acc1 = 0.f;
#pragma unroll
        for (int d4 = 0; d4 < 32; d4 += 4) {
            float4 qv = *(const float4*)&qs[i][d4];
            acc0 += qv.x * kst[d4 + 0][lane] + qv.y * kst[d4 + 1][lane]
                  + qv.z * kst[d4 + 2][lane] + qv.w * kst[d4 + 3][lane];
            acc1 += qv.x * kst[d4 + 0][lane + 32] + qv.y * kst[d4 + 1][lane + 32]
                  + qv.z * kst[d4 + 2][lane + 32] + qv.w * kst[d4 + 3][lane + 32];
        }
        const int idx0 = (yi - yj0 + 7) * 15 + (xi - xj0 + 7);
        const int idx1 = (yi - yj1 + 7) * 15 + (xi - xj1 + 7);
        float s0 = acc0 + bt[idx0] + mrow[i * 64 + lane];
        float s1 = acc1 + bt[idx1] + mrow[i * 64 + lane + 32];

        float m = fmaxf(s0, s1);
#pragma unroll
        for (int o = 16; o > 0; o >>= 1)
            m = fmaxf(m, __shfl_xor_sync(0xffffffffu, m, o));
        float e0 = __expf(s0 - m);
        float e1 = __expf(s1 - m);
        float sum = e0 + e1;
#pragma unroll
        for (int o = 16; o > 0; o >>= 1)
            sum += __shfl_xor_sync(0xffffffffu, sum, o);
        const float inv = 1.f / sum;
        ps[i][lane]      = e0 * inv;
        ps[i][lane + 32] = e1 * inv;
    }

#pragma unroll 1
    for (int r = 0; r < 8; r++) {
        const int i = warp * 8 + r;
        float acc = 0.f;
#pragma unroll
        for (int j = 0; j < 64; j += 4) {
            float4 p = *(const float4*)&ps[i][j];
            acc += p.x * vs[j + 0][lane] + p.y * vs[j + 1][lane]
                 + p.z * vs[j + 2][lane] + p.w * vs[j + 3][lane];
        }
        // emit bf16 hi/lo split directly for the HMMA proj GEMM
        const size_t idx = ((size_t)b * 64 + i) * DIM + h * 32 + lane;
        __nv_bfloat16 hi = __float2bfloat16(acc);
        __nv_bfloat16 lo = __float2bfloat16(acc - __bfloat162float(hi));
        g_ao_hi[idx] = hi;
        g_ao_lo[idx] = lo;
    }
}

// ---------------- launch ----------------------------------------------------
extern "C" void kernel_launch(void* const* d_in, const int* in_sizes, int n_in,
                              void* d_out, int out_size)
{
    const float* x          = (const float*)d_in[0]; // (2048,64,256)
    const float* mask       = (const float*)d_in[1]; // (2048,1,64,64)
    const float* w_qkv      = (const float*)d_in[2]; // (768,256)
    const float* b_qkv      = (const float*)d_in[3]; // (768)
    const float* w_proj     = (const float*)d_in[4]; // (256,256)
    const float* b_proj     = (const float*)d_in[5]; // (256)
    const float* bias_table = (const float*)d_in[6]; // (225,8)
    float* out = (float*)d_out;                      // (2048,64,256)

    (void)in_sizes; (void)n_in; (void)out_size;

    __nv_bfloat16 *xh, *xl, *wqh, *wql, *wph, *wpl, *aoh, *aol;
    cudaGetSymbolAddress((void**)&xh,  g_x_hi);
    cudaGetSymbolAddress((void**)&xl,  g_x_lo);
    cudaGetSymbolAddress((void**)&wqh, g_wq_hi);
    cudaGetSymbolAddress((void**)&wql, g_wq_lo);
    cudaGetSymbolAddress((void**)&wph, g_wp_hi);
    cudaGetSymbolAddress((void**)&wpl, g_wp_lo);
    cudaGetSymbolAddress((void**)&aoh, g_ao_hi);
    cudaGetSymbolAddress((void**)&aol, g_ao_lo);

    cudaFuncSetAttribute(gemm_mma<0>, cudaFuncAttributeMaxDynamicSharedMemorySize, GEMM_SMEM);
    cudaFuncSetAttribute(gemm_mma<1>, cudaFuncAttributeMaxDynamicSharedMemorySize, GEMM_SMEM);

    // 0) fp32 -> bf16 hi/lo splits
    {
        int n4 = (MROWS * DIM) / 4;
        convert_split<<<(n4 + 255) / 256, 256>>>(x, xh, xl, n4);
        int w4 = (QKVDIM * DIM) / 4;
        convert_split<<<(w4 + 255) / 256, 256>>>(w_qkv, wqh, wql, w4);
        int p4 = (DIM * DIM) / 4;
        convert_split<<<(p4 + 255) / 256, 256>>>(w_proj, wph, wpl, p4);
    }
    // 1) QKV GEMM (HMMA) -> g_qkv (q pre-scaled)
    {
        dim3 grid(QKVDIM / 64, MROWS / 128);   // 12 x 1024
        gemm_mma<0><<<grid, 256, GEMM_SMEM>>>(xh, xl, wqh, wql, b_qkv, nullptr);
    }
    // 2) windowed attention -> g_ao hi/lo
    attn_kernel<<<B_WIN * NHEADS, 256>>>(mask, bias_table);
    // 3) output projection (HMMA) -> out
    {
        dim3 grid(DIM / 64, MROWS / 128);      // 4 x 1024
        gemm_mma<1><<<grid, 256, GEMM_SMEM>>>(aoh, aol, wph, wpl, b_proj, out);
    }
}

// round 5
// speedup vs baseline: 2.7806x; 1.3558x over previous
#include <cuda_runtime.h>
#include <cuda_bf16.h>
#include <cstdint>

#define B_WIN   2048
#define NTOK    64
#define DIM     256
#define NHEADS  8
#define QKVDIM  768
#define MROWS   (B_WIN * NTOK)          // 131072
#define SCALE   0.17677669529663687f    // 32^-0.5

// ---------------- scratch (device globals; no cudaMalloc allowed) ----------
#define HEAD_ELEMS (2048ull * 8ull * 64ull * 32ull)   // 33.5M per plane
__device__ __nv_bfloat16 g_q_hi[HEAD_ELEMS],  g_q_lo[HEAD_ELEMS];
__device__ __nv_bfloat16 g_k_hi[HEAD_ELEMS],  g_k_lo[HEAD_ELEMS];
__device__ __nv_bfloat16 g_vt_hi[HEAD_ELEMS], g_vt_lo[HEAD_ELEMS];  // [bh][d][n]
__device__ __nv_bfloat16 g_x_hi[(size_t)MROWS * DIM];
__device__ __nv_bfloat16 g_x_lo[(size_t)MROWS * DIM];
__device__ __nv_bfloat16 g_ao_hi[(size_t)MROWS * DIM];
__device__ __nv_bfloat16 g_ao_lo[(size_t)MROWS * DIM];
__device__ __nv_bfloat16 g_wq_hi[QKVDIM * DIM];
__device__ __nv_bfloat16 g_wq_lo[QKVDIM * DIM];
__device__ __nv_bfloat16 g_wp_hi[DIM * DIM];
__device__ __nv_bfloat16 g_wp_lo[DIM * DIM];

// ================= helpers ==================================================
__device__ __forceinline__ uint32_t smem_u32(const void* p) {
    uint32_t a;
    asm("{ .reg .u64 t; cvta.to.shared.u64 t, %1; cvt.u32.u64 %0, t; }"
        : "=r"(a) : "l"(p));
    return a;
}

__device__ __forceinline__ void ldsm_x4(uint32_t* r, uint32_t addr) {
    asm volatile("ldmatrix.sync.aligned.m8n8.x4.shared.b16 {%0,%1,%2,%3}, [%4];"
                 : "=r"(r[0]), "=r"(r[1]), "=r"(r[2]), "=r"(r[3]) : "r"(addr));
}

// D += A(bf16 16x16) * B(bf16 16x8), fp32 accumulate
__device__ __forceinline__ void mma16816(float* c, const uint32_t* a, const uint32_t* b) {
    asm volatile("mma.sync.aligned.m16n8k16.row.col.f32.bf16.bf16.f32 "
                 "{%0,%1,%2,%3}, {%4,%5,%6,%7}, {%8,%9}, {%0,%1,%2,%3};"
                 : "+f"(c[0]), "+f"(c[1]), "+f"(c[2]), "+f"(c[3])
                 : "r"(a[0]), "r"(a[1]), "r"(a[2]), "r"(a[3]),
                   "r"(b[0]), "r"(b[1]));
}

__device__ __forceinline__ uint32_t pack_bf16x2(float x, float y) {
    __nv_bfloat162 t = __floats2bfloat162_rn(x, y);
    return *(uint32_t*)&t;
}

// ================= fp32 -> (hi, lo) bf16 split =============================
__global__ void convert_split(const float* __restrict__ src,
                              __nv_bfloat16* __restrict__ hi,
                              __nv_bfloat16* __restrict__ lo, int n4)
{
    int i = blockIdx.x * blockDim.x + threadIdx.x;
    if (i >= n4) return;
    float4 v = ((const float4*)src)[i];
    float f[4] = {v.x, v.y, v.z, v.w};
    __nv_bfloat16 h[4], l[4];
#pragma unroll
    for (int k = 0; k < 4; k++) {
        h[k] = __float2bfloat16(f[k]);
        l[k] = __float2bfloat16(f[k] - __bfloat162float(h[k]));
    }
    ((__nv_bfloat162*)hi)[2*i]   = __halves2bfloat162(h[0], h[1]);
    ((__nv_bfloat162*)hi)[2*i+1] = __halves2bfloat162(h[2], h[3]);
    ((__nv_bfloat162*)lo)[2*i]   = __halves2bfloat162(l[0], l[1]);
    ((__nv_bfloat162*)lo)[2*i+1] = __halves2bfloat162(l[2], l[3]);
}

// ================= HMMA GEMM ================================================
// C[128 x 64] block tile = A[128 x 256] * W[64 x 256]^T  (3-term bf16 split)
// 8 warps: 4(M) x 2(N), warp tile 32x32 via mma.m16n8k16.
// MODE 0: epilogue splits into q/k/vt bf16 hi/lo planes (q scaled).
// MODE 1: writes fp32 `out`.

#define SSTR  72                    // bf16 per smem row (144B, conflict-free)
#define OFF_AH 0
#define OFF_AL 18432
#define OFF_BH 36864
#define OFF_BL 46080
#define GEMM_SMEM 55296

template <int MODE>
__global__ void __launch_bounds__(256)
gemm_mma(const __nv_bfloat16* __restrict__ Ah, const __nv_bfloat16* __restrict__ Al,
         const __nv_bfloat16* __restrict__ Wh, const __nv_bfloat16* __restrict__ Wl,
         const float* __restrict__ bias, float* __restrict__ out)
{
    extern __shared__ char smem[];
    __nv_bfloat16* sAh = (__nv_bfloat16*)(smem + OFF_AH);
    __nv_bfloat16* sAl = (__nv_bfloat16*)(smem + OFF_AL);
    __nv_bfloat16* sBh = (__nv_bfloat16*)(smem + OFF_BH);
    __nv_bfloat16* sBl = (__nv_bfloat16*)(smem + OFF_BL);

    const int tid  = threadIdx.x;
    const int lane = tid & 31;
    const int warp = tid >> 5;
    const int wm   = warp >> 1;          // 0..3
    const int wn   = warp & 1;           // 0..1
    const int row0 = blockIdx.y * 128;
    const int col0 = blockIdx.x * 64;

    float acc[2][4][4];
#pragma unroll
    for (int a = 0; a < 2; a++)
#pragma unroll
        for (int b = 0; b < 4; b++)
#pragma unroll
            for (int c = 0; c < 4; c++) acc[a][b][c] = 0.f;

    const int a_row = wm * 32 + (lane & 15);
    const int a_ksel = (lane >> 4) * 8;
    const int b_row = wn * 32 + ((lane >> 4) << 3) + (lane & 7);
    const int b_ksel = ((lane >> 3) & 1) << 3;

    for (int kc = 0; kc < 4; kc++) {
        const int k0 = kc * 64;
        __syncthreads();
#pragma unroll
        for (int t = 0; t < 4; t++) {
            const int idx = tid + t * 256;
            const int r = idx >> 3, c8 = (idx & 7) * 8;
            const size_t go = (size_t)(row0 + r) * 256 + k0 + c8;
            *(uint4*)(sAh + r * SSTR + c8) = *(const uint4*)(Ah + go);
            *(uint4*)(sAl + r * SSTR + c8) = *(const uint4*)(Al + go);
        }
#pragma unroll
        for (int t = 0; t < 2; t++) {
            const int idx = tid + t * 256;
            const int r = idx >> 3, c8 = (idx & 7) * 8;
            const size_t go = (size_t)(col0 + r) * 256 + k0 + c8;
            *(uint4*)(sBh + r * SSTR + c8) = *(const uint4*)(Wh + go);
            *(uint4*)(sBl + r * SSTR + c8) = *(const uint4*)(Wl + go);
        }
        __syncthreads();

#pragma unroll
        for (int kk = 0; kk < 64; kk += 16) {
            uint32_t a_h[2][4], a_l[2][4], b_h[2][4], b_l[2][4];
#pragma unroll
            for (int mt = 0; mt < 2; mt++) {
                const int off = (a_row + mt * 16) * SSTR + kk + a_ksel;
                ldsm_x4(a_h[mt], smem_u32(sAh + off));
                ldsm_x4(a_l[mt], smem_u32(sAl + off));
            }
#pragma unroll
            for (int g = 0; g < 2; g++) {
                const int off = (b_row + g * 16) * SSTR + kk + b_ksel;
                ldsm_x4(b_h[g], smem_u32(sBh + off));
                ldsm_x4(b_l[g], smem_u32(sBl + off));
            }
#pragma unroll
            for (int mt = 0; mt < 2; mt++)
#pragma unroll
                for (int g = 0; g < 2; g++)
#pragma unroll
                    for (int j = 0; j < 2; j++) {
                        float* c = acc[mt][g * 2 + j];
                        mma16816(c, a_h[mt], &b_h[g][j * 2]);
                        mma16816(c, a_h[mt], &b_l[g][j * 2]);
                        mma16816(c, a_l[mt], &b_h[g][j * 2]);
                    }
        }
    }

    // epilogue
    const int gid = lane >> 2, tig = lane & 3;
#pragma unroll
    for (int mt = 0; mt < 2; mt++)
#pragma unroll
        for (int g = 0; g < 2; g++)
#pragma unroll
            for (int j = 0; j < 2; j++) {
                const int nf = g * 2 + j;
                const int col = col0 + wn * 32 + g * 16 + j * 8 + tig * 2;
                const float2 bv = *(const float2*)(bias + col);
#pragma unroll
                for (int rs = 0; rs < 2; rs++) {
                    const int row = row0 + wm * 32 + mt * 16 + gid + rs * 8;
                    float v0 = acc[mt][nf][rs * 2 + 0] + bv.x;
                    float v1 = acc[mt][nf][rs * 2 + 1] + bv.y;
                    if (MODE == 0) {
                        const int s = col >> 8;
                        if (s == 0) { v0 *= SCALE; v1 *= SCALE; }
                        __nv_bfloat16 h0 = __float2bfloat16(v0);
                        __nv_bfloat16 l0 = __float2bfloat16(v0 - __bfloat162float(h0));
                        __nv_bfloat16 h1 = __float2bfloat16(v1);
                        __nv_bfloat16 l1 = __float2bfloat16(v1 - __bfloat162float(h1));
                        const int hh = (col >> 5) & 7, d = col & 31;
                        const int b = row >> 6, n = row & 63;
                        const size_t pb = (size_t)(b * 8 + hh) * 2048;
                        if (s == 0) {
                            *(__nv_bfloat162*)(g_q_hi + pb + n * 32 + d) = __halves2bfloat162(h0, h1);
                            *(__nv_bfloat162*)(g_q_lo + pb + n * 32 + d) = __halves2bfloat162(l0, l1);
                        } else if (s == 1) {
                            *(__nv_bfloat162*)(g_k_hi + pb + n * 32 + d) = __halves2bfloat162(h0, h1);
                            *(__nv_bfloat162*)(g_k_lo + pb + n * 32 + d) = __halves2bfloat162(l0, l1);
                        } else {   // v, stored transposed [d][n]
                            g_vt_hi[pb + (size_t)d * 64 + n]       = h0;
                            g_vt_hi[pb + (size_t)(d + 1) * 64 + n] = h1;
                            g_vt_lo[pb + (size_t)d * 64 + n]       = l0;
                            g_vt_lo[pb + (size_t)(d + 1) * 64 + n] = l1;
                        }
                    } else {
                        *(float2*)(out + (size_t)row * 256 + col)
                            = make_float2(v0, v1);
                    }
                }
            }
}

// ================= HMMA attention: one (window, head) per CTA ===============
// 4 warps x 16 query rows. QK^T and P*V on tensor cores, 3-term bf16 split.
#define QSTR 40   // smem stride for 32-col tiles (80B = 5*16B, LDSM conflict-free)
#define VSTR 72   // smem stride for 64-col V^T tile

__global__ void __launch_bounds__(128)
attn_mma(const float* __restrict__ mask, const float* __restrict__ bias_table)
{
    const int bh = blockIdx.x;
    const int b  = bh >> 3;
    const int h  = bh & 7;

    __shared__ __nv_bfloat16 sQh[64 * QSTR], sQl[64 * QSTR];
    __shared__ __nv_bfloat16 sKh[64 * QSTR], sKl[64 * QSTR];
    __shared__ __nv_bfloat16 sVh[32 * VSTR], sVl[32 * VSTR];
    __shared__ float bt[228];

    const int tid  = threadIdx.x;
    const int warp = tid >> 5;
    const int lane = tid & 31;

    const __nv_bfloat16* Qh = g_q_hi  + (size_t)bh * 2048;
    const __nv_bfloat16* Ql = g_q_lo  + (size_t)bh * 2048;
    const __nv_bfloat16* Kh = g_k_hi  + (size_t)bh * 2048;
    const __nv_bfloat16* Kl = g_k_lo  + (size_t)bh * 2048;
    const __nv_bfloat16* Vh = g_vt_hi + (size_t)bh * 2048;
    const __nv_bfloat16* Vl = g_vt_lo + (size_t)bh * 2048;

    // stage tiles (uint4 = 8 bf16 per chunk; 256 chunks per plane)
    for (int c = tid; c < 256; c += 128) {
        const int qr = c >> 2, qc = (c & 3) * 8;     // q/k: rows of 32
        *(uint4*)(sQh + qr * QSTR + qc) = *(const uint4*)(Qh + c * 8);
        *(uint4*)(sQl + qr * QSTR + qc) = *(const uint4*)(Ql + c * 8);
        *(uint4*)(sKh + qr * QSTR + qc) = *(const uint4*)(Kh + c * 8);
        *(uint4*)(sKl + qr * QSTR + qc) = *(const uint4*)(Kl + c * 8);
        const int vr = c >> 3, vc = (c & 7) * 8;     // v^T: rows of 64
        *(uint4*)(sVh + vr * VSTR + vc) = *(const uint4*)(Vh + c * 8);
        *(uint4*)(sVl + vr * VSTR + vc) = *(const uint4*)(Vl + c * 8);
    }
    for (int t = tid; t < 225; t += 128) bt[t] = bias_table[t * NHEADS + h];
    __syncthreads();

    const int gid = lane >> 2, tig = lane & 3;
    const int a_rowoff = (warp * 16 + (lane & 15)) * QSTR + (lane >> 4) * 8;
    const int b_row    = ((lane >> 4) << 3) + (lane & 7);
    const int b_ksel   = ((lane >> 3) & 1) << 3;

    // ---- QK^T: scores 16x64 per warp --------------------------------------
    float acc[8][4];
#pragma unroll
    for (int nt = 0; nt < 8; nt++)
#pragma unroll
        for (int c = 0; c < 4; c++) acc[nt][c] = 0.f;

#pragma unroll
    for (int kt = 0; kt < 2; kt++) {
        uint32_t qh[4], ql[4];
        ldsm_x4(qh, smem_u32(sQh + a_rowoff + kt * 16));
        ldsm_x4(ql, smem_u32(sQl + a_rowoff + kt * 16));
#pragma unroll
        for (int ng = 0; ng < 4; ng++) {
            uint32_t kh[4], kl[4];
            const int off = (ng * 16 + b_row) * QSTR + kt * 16 + b_ksel;
            ldsm_x4(kh, smem_u32(sKh + off));
            ldsm_x4(kl, smem_u32(sKl + off));
#pragma unroll
            for (int j = 0; j < 2; j++) {
                float* c = acc[ng * 2 + j];
                mma16816(c, qh, &kh[j * 2]);
                mma16816(c, qh, &kl[j * 2]);
                mma16816(c, ql, &kh[j * 2]);
            }
        }
    }

    // ---- bias + mask in fragment layout ------------------------------------
    const int i0 = warp * 16 + gid, i1 = i0 + 8;
    const int yi0 = i0 >> 3, xi0 = i0 & 7;
    const int yi1 = i1 >> 3, xi1 = i1 & 7;
    const float* mrow = mask + (size_t)b * 4096;
#pragma unroll
    for (int nt = 0; nt < 8; nt++) {
        const int col = nt * 8 + tig * 2;           // yj = nt, xj = 2tig, 2tig+1
        const float2 m0 = *(const float2*)(mrow + i0 * 64 + col);
        const float2 m1 = *(const float2*)(mrow + i1 * 64 + col);
        acc[nt][0] += bt[(yi0 - nt + 7) * 15 + (xi0 - tig * 2 + 7)] + m0.x;
        acc[nt][1] += bt[(yi0 - nt + 7) * 15 + (xi0 - tig * 2 + 6)] + m0.y;
        acc[nt][2] += bt[(yi1 - nt + 7) * 15 + (xi1 - tig * 2 + 7)] + m1.x;
        acc[nt][3] += bt[(yi1 - nt + 7) * 15 + (xi1 - tig * 2 + 6)] + m1.y;
    }

    // ---- softmax (rows live in lane quads) ----------------------------------
    float mx0 = -1e30f, mx1 = -1e30f;
#pragma unroll
    for (int nt = 0; nt < 8; nt++) {
        mx0 = fmaxf(mx0, fmaxf(acc[nt][0], acc[nt][1]));
        mx1 = fmaxf(mx1, fmaxf(acc[nt][2], acc[nt][3]));
    }
    mx0 = fmaxf(mx0, __shfl_xor_sync(0xffffffffu, mx0, 1));
    mx0 = fmaxf(mx0, __shfl_xor_sync(0xffffffffu, mx0, 2));
    mx1 = fmaxf(mx1, __shfl_xor_sync(0xffffffffu, mx1, 1));
    mx1 = fmaxf(mx1, __shfl_xor_sync(0xffffffffu, mx1, 2));

    float sum0 = 0.f, sum1 = 0.f;
#pragma unroll
    for (int nt = 0; nt < 8; nt++) {
        acc[nt][0] = __expf(acc[nt][0] - mx0);
        acc[nt][1] = __expf(acc[nt][1] - mx0);
        acc[nt][2] = __expf(acc[nt][2] - mx1);
        acc[nt][3] = __expf(acc[nt][3] - mx1);
        sum0 += acc[nt][0] + acc[nt][1];
        sum1 += acc[nt][2] + acc[nt][3];
    }
    sum0 += __shfl_xor_sync(0xffffffffu, sum0, 1);
    sum0 += __shfl_xor_sync(0xffffffffu, sum0, 2);
    sum1 += __shfl_xor_sync(0xffffffffu, sum1, 1);
    sum1 += __shfl_xor_sync(0xffffffffu, sum1, 2);
    const float inv0 = 1.f / sum0, inv1 = 1.f / sum1;

    // ---- repack P into A-fragments (hi/lo split) ----------------------------
    uint32_t phi[4][4], plo[4][4];
#pragma unroll
    for (int kt = 0; kt < 4; kt++) {
        const float p00 = acc[kt*2][0] * inv0,   p01 = acc[kt*2][1] * inv0;
        const float p10 = acc[kt*2][2] * inv1,   p11 = acc[kt*2][3] * inv1;
        const float p20 = acc[kt*2+1][0] * inv0, p21 = acc[kt*2+1][1] * inv0;
        const float p30 = acc[kt*2+1][2] * inv1, p31 = acc[kt*2+1][3] * inv1;
        const float f[4][2] = {{p00,p01},{p10,p11},{p20,p21},{p30,p31}};
#pragma unroll
        for (int r = 0; r < 4; r++) {
            __nv_bfloat16 hx = __float2bfloat16(f[r][0]);
            __nv_bfloat16 hy = __float2bfloat16(f[r][1]);
            phi[kt][r] = pack_bf16x2(f[r][0], f[r][1]);
            plo[kt][r] = pack_bf16x2(f[r][0] - __bfloat162float(hx),
                                     f[r][1] - __bfloat162float(hy));
        }
    }

    // ---- P * V : out 16x32 per warp -----------------------------------------
    float ao[4][4];
#pragma unroll
    for (int dn = 0; dn < 4; dn++)
#pragma unroll
        for (int c = 0; c < 4; c++) ao[dn][c] = 0.f;

#pragma unroll
    for (int kt = 0; kt < 4; kt++) {
#pragma unroll
        for (int g = 0; g < 2; g++) {
            uint32_t vh[4], vl[4];
            const int off = (g * 16 + b_row) * VSTR + kt * 16 + b_ksel;
            ldsm_x4(vh, smem_u32(sVh + off));
            ldsm_x4(vl, smem_u32(sVl + off));
#pragma unroll
            for (int j = 0; j < 2; j++) {
                float* c = ao[g * 2 + j];
                mma16816(c, phi[kt], &vh[j * 2]);
                mma16816(c, phi[kt], &vl[j * 2]);
                mma16816(c, plo[kt], &vh[j * 2]);
            }
        }
    }

    // ---- epilogue: split to bf16 hi/lo for the proj GEMM --------------------
#pragma unroll
    for (int dn = 0; dn < 4; dn++) {
        const int d = dn * 8 + tig * 2;
#pragma unroll
        for (int rs = 0; rs < 2; rs++) {
            const int row = rs ? i1 : i0;
            const float v0 = ao[dn][rs * 2 + 0];
            const float v1 = ao[dn][rs * 2 + 1];
            __nv_bfloat16 h0 = __float2bfloat16(v0);
            __nv_bfloat16 l0 = __float2bfloat16(v0 - __bfloat162float(h0));
            __nv_bfloat16 h1 = __float2bfloat16(v1);
            __nv_bfloat16 l1 = __float2bfloat16(v1 - __bfloat162float(h1));
            const size_t o = ((size_t)b * 64 + row) * DIM + h * 32 + d;
            *(__nv_bfloat162*)(g_ao_hi + o) = __halves2bfloat162(h0, h1);
            *(__nv_bfloat162*)(g_ao_lo + o) = __halves2bfloat162(l0, l1);
        }
    }
}

// ---------------- launch ----------------------------------------------------
extern "C" void kernel_launch(void* const* d_in, const int* in_sizes, int n_in,
                              void* d_out, int out_size)
{
    const float* x          = (const float*)d_in[0]; // (2048,64,256)
    const float* mask       = (const float*)d_in[1]; // (2048,1,64,64)
    const float* w_qkv      = (const float*)d_in[2]; // (768,256)
    const float* b_qkv      = (const float*)d_in[3]; // (768)
    const float* w_proj     = (const float*)d_in[4]; // (256,256)
    const float* b_proj     = (const float*)d_in[5]; // (256)
    const float* bias_table = (const float*)d_in[6]; // (225,8)
    float* out = (float*)d_out;                      // (2048,64,256)

    (void)in_sizes; (void)n_in; (void)out_size;

    __nv_bfloat16 *xh, *xl, *wqh, *wql, *wph, *wpl, *aoh, *aol;
    cudaGetSymbolAddress((void**)&xh,  g_x_hi);
    cudaGetSymbolAddress((void**)&xl,  g_x_lo);
    cudaGetSymbolAddress((void**)&wqh, g_wq_hi);
    cudaGetSymbolAddress((void**)&wql, g_wq_lo);
    cudaGetSymbolAddress((void**)&wph, g_wp_hi);
    cudaGetSymbolAddress((void**)&wpl, g_wp_lo);
    cudaGetSymbolAddress((void**)&aoh, g_ao_hi);
    cudaGetSymbolAddress((void**)&aol, g_ao_lo);

    cudaFuncSetAttribute(gemm_mma<0>, cudaFuncAttributeMaxDynamicSharedMemorySize, GEMM_SMEM);
    cudaFuncSetAttribute(gemm_mma<1>, cudaFuncAttributeMaxDynamicSharedMemorySize, GEMM_SMEM);

    // 0) fp32 -> bf16 hi/lo splits
    {
        int n4 = (MROWS * DIM) / 4;
        convert_split<<<(n4 + 255) / 256, 256>>>(x, xh, xl, n4);
        int w4 = (QKVDIM * DIM) / 4;
        convert_split<<<(w4 + 255) / 256, 256>>>(w_qkv, wqh, wql, w4);
        int p4 = (DIM * DIM) / 4;
        convert_split<<<(p4 + 255) / 256, 256>>>(w_proj, wph, wpl, p4);
    }
    // 1) QKV GEMM (HMMA) -> q/k/vt bf16 hi/lo planes (q pre-scaled)
    {
        dim3 grid(QKVDIM / 64, MROWS / 128);   // 12 x 1024
        gemm_mma<0><<<grid, 256, GEMM_SMEM>>>(xh, xl, wqh, wql, b_qkv, nullptr);
    }
    // 2) windowed attention (HMMA) -> g_ao hi/lo
    attn_mma<<<B_WIN * NHEADS, 128>>>(mask, bias_table);
    // 3) output projection (HMMA) -> out
    {
        dim3 grid(DIM / 64, MROWS / 128);      // 4 x 1024
        gemm_mma<1><<<grid, 256, GEMM_SMEM>>>(aoh, aol, wph, wpl, b_proj, out);
    }
}

// round 6
// speedup vs baseline: 3.0551x; 1.0987x over previous
#include <cuda_runtime.h>
#include <cuda_bf16.h>
#include <cstdint>

#define B_WIN   2048
#define NTOK    64
#define DIM     256
#define NHEADS  8
#define QKVDIM  768
#define MROWS   (B_WIN * NTOK)          // 131072
#define SCALE   0.17677669529663687f    // 32^-0.5

// ---------------- scratch (device globals; no cudaMalloc allowed) ----------
#define HEAD_ELEMS (2048ull * 8ull * 64ull * 32ull)   // 33.5M per plane
__device__ __nv_bfloat16 g_q_hi[HEAD_ELEMS],  g_q_lo[HEAD_ELEMS];
__device__ __nv_bfloat16 g_k_hi[HEAD_ELEMS],  g_k_lo[HEAD_ELEMS];
__device__ __nv_bfloat16 g_vt_hi[HEAD_ELEMS], g_vt_lo[HEAD_ELEMS];  // [bh][d][n]
__device__ __nv_bfloat16 g_x_hi[(size_t)MROWS * DIM];
__device__ __nv_bfloat16 g_x_lo[(size_t)MROWS * DIM];
__device__ __nv_bfloat16 g_ao_hi[(size_t)MROWS * DIM];
__device__ __nv_bfloat16 g_ao_lo[(size_t)MROWS * DIM];
__device__ __nv_bfloat16 g_wq_hi[QKVDIM * DIM];
__device__ __nv_bfloat16 g_wq_lo[QKVDIM * DIM];
__device__ __nv_bfloat16 g_wp_hi[DIM * DIM];
__device__ __nv_bfloat16 g_wp_lo[DIM * DIM];

// ================= helpers ==================================================
__device__ __forceinline__ uint32_t smem_u32(const void* p) {
    uint32_t a;
    asm("{ .reg .u64 t; cvta.to.shared.u64 t, %1; cvt.u32.u64 %0, t; }"
        : "=r"(a) : "l"(p));
    return a;
}

__device__ __forceinline__ void ldsm_x4(uint32_t* r, uint32_t addr) {
    asm volatile("ldmatrix.sync.aligned.m8n8.x4.shared.b16 {%0,%1,%2,%3}, [%4];"
                 : "=r"(r[0]), "=r"(r[1]), "=r"(r[2]), "=r"(r[3]) : "r"(addr));
}

// D += A(bf16 16x16) * B(bf16 16x8), fp32 accumulate
__device__ __forceinline__ void mma16816(float* c, const uint32_t* a, const uint32_t* b) {
    asm volatile("mma.sync.aligned.m16n8k16.row.col.f32.bf16.bf16.f32 "
                 "{%0,%1,%2,%3}, {%4,%5,%6,%7}, {%8,%9}, {%0,%1,%2,%3};"
                 : "+f"(c[0]), "+f"(c[1]), "+f"(c[2]), "+f"(c[3])
                 : "r"(a[0]), "r"(a[1]), "r"(a[2]), "r"(a[3]),
                   "r"(b[0]), "r"(b[1]));
}

__device__ __forceinline__ uint32_t pack_bf16x2(float x, float y) {
    __nv_bfloat162 t = __floats2bfloat162_rn(x, y);
    return *(uint32_t*)&t;
}

__device__ __forceinline__ void cp16(uint32_t dst, const void* src) {
    asm volatile("cp.async.cg.shared.global [%0], [%1], 16;"
                 :: "r"(dst), "l"(src) : "memory");
}
#define CP_COMMIT() asm volatile("cp.async.commit_group;" ::: "memory")

// ================= fp32 -> (hi, lo) bf16 split =============================
__global__ void convert_split(const float* __restrict__ src,
                              __nv_bfloat16* __restrict__ hi,
                              __nv_bfloat16* __restrict__ lo, int n4)
{
    int i = blockIdx.x * blockDim.x + threadIdx.x;
    if (i >= n4) return;
    float4 v = ((const float4*)src)[i];
    float f[4] = {v.x, v.y, v.z, v.w};
    __nv_bfloat16 h[4], l[4];
#pragma unroll
    for (int k = 0; k < 4; k++) {
        h[k] = __float2bfloat16(f[k]);
        l[k] = __float2bfloat16(f[k] - __bfloat162float(h[k]));
    }
    ((__nv_bfloat162*)hi)[2*i]   = __halves2bfloat162(h[0], h[1]);
    ((__nv_bfloat162*)hi)[2*i+1] = __halves2bfloat162(h[2], h[3]);
    ((__nv_bfloat162*)lo)[2*i]   = __halves2bfloat162(l[0], l[1]);
    ((__nv_bfloat162*)lo)[2*i+1] = __halves2bfloat162(l[2], l[3]);
}

// ================= HMMA GEMM (cp.async double-buffered) ====================
// C[128 x 64] block tile = A[128 x 256] * W[64 x 256]^T  (3-term bf16 split)
// 8 warps: 4(M) x 2(N), warp tile 32x32 via mma.m16n8k16. BK=64, 2 stages.
// MODE 0: epilogue splits into q/k/vt bf16 hi/lo planes (q scaled).
// MODE 1: writes fp32 `out`.

#define SSTR    72                  // bf16 per smem row (144B, conflict-free)
#define SROWB   144                 // bytes per smem row
#define OFF_AH  0
#define OFF_AL  18432
#define OFF_BH  36864
#define OFF_BL  46080
#define STAGE   55296
#define GEMM_SMEM (2 * STAGE)       // 110592 bytes

template <int MODE>
__global__ void __launch_bounds__(256)
gemm_mma(const __nv_bfloat16* __restrict__ Ah, const __nv_bfloat16* __restrict__ Al,
         const __nv_bfloat16* __restrict__ Wh, const __nv_bfloat16* __restrict__ Wl,
         const float* __restrict__ bias, float* __restrict__ out)
{
    extern __shared__ char smem[];
    const uint32_t sb = smem_u32(smem);

    const int tid  = threadIdx.x;
    const int lane = tid & 31;
    const int warp = tid >> 5;
    const int wm   = warp >> 1;          // 0..3
    const int wn   = warp & 1;           // 0..1
    const int row0 = blockIdx.y * 128;
    const int col0 = blockIdx.x * 64;

    float acc[2][4][4];
#pragma unroll
    for (int a = 0; a < 2; a++)
#pragma unroll
        for (int b = 0; b < 4; b++)
#pragma unroll
            for (int c = 0; c < 4; c++) acc[a][b][c] = 0.f;

    // per-thread load geometry (16B chunks)
    const int lr_a = tid >> 3;                   // A row step base (per 256 thr: 32 rows)
    const int lc   = (tid & 7) * 8;              // element col within 64
    const uint32_t so_base = (uint32_t)(tid >> 3) * SROWB + (tid & 7) * 16;

    // ldmatrix lane addressing (element offsets)
    const int a_row  = wm * 32 + (lane & 15);
    const int a_ksel = (lane >> 4) * 8;
    const int b_row  = wn * 32 + ((lane >> 4) << 3) + (lane & 7);
    const int b_ksel = ((lane >> 3) & 1) << 3;

    // ---- async stage issue ---------------------------------------------------
    auto issue = [&](int kc, uint32_t stb) {
        const int k0 = kc * 64;
#pragma unroll
        for (int t = 0; t < 4; t++) {            // A: 128 rows
            const int r = lr_a + t * 32;
            const uint32_t so = so_base + t * 32 * SROWB;
            const size_t go = (size_t)(row0 + r) * 256 + k0 + lc;
            cp16(stb + OFF_AH + so, Ah + go);
            cp16(stb + OFF_AL + so, Al + go);
        }
#pragma unroll
        for (int t = 0; t < 2; t++) {            // B: 64 rows
            const int r = lr_a + t * 32;
            const uint32_t so = so_base + t * 32 * SROWB;
            const size_t go = (size_t)(col0 + r) * 256 + k0 + lc;
            cp16(stb + OFF_BH + so, Wh + go);
            cp16(stb + OFF_BL + so, Wl + go);
        }
    };

    issue(0, sb);
    CP_COMMIT();

    for (int kc = 0; kc < 4; kc++) {
        if (kc < 3) {
            issue(kc + 1, sb + ((kc + 1) & 1) * STAGE);
            CP_COMMIT();
            asm volatile("cp.async.wait_group 1;" ::: "memory");
        } else {
            asm volatile("cp.async.wait_group 0;" ::: "memory");
        }
        __syncthreads();

        const uint32_t stb = sb + (kc & 1) * STAGE;
#pragma unroll
        for (int kk = 0; kk < 64; kk += 16) {
            uint32_t a_h[2][4], a_l[2][4], b_h[2][4], b_l[2][4];
#pragma unroll
            for (int mt = 0; mt < 2; mt++) {
                const uint32_t off = (uint32_t)(a_row + mt * 16) * SROWB
                                   + (kk + a_ksel) * 2;
                ldsm_x4(a_h[mt], stb + OFF_AH + off);
                ldsm_x4(a_l[mt], stb + OFF_AL + off);
            }
#pragma unroll
            for (int g = 0; g < 2; g++) {
                const uint32_t off = (uint32_t)(b_row + g * 16) * SROWB
                                   + (kk + b_ksel) * 2;
                ldsm_x4(b_h[g], stb + OFF_BH + off);
                ldsm_x4(b_l[g], stb + OFF_BL + off);
            }
#pragma unroll
            for (int mt = 0; mt < 2; mt++)
#pragma unroll
                for (int g = 0; g < 2; g++)
#pragma unroll
                    for (int j = 0; j < 2; j++) {
                        float* c = acc[mt][g * 2 + j];
                        mma16816(c, a_h[mt], &b_h[g][j * 2]);
                        mma16816(c, a_h[mt], &b_l[g][j * 2]);
                        mma16816(c, a_l[mt], &b_h[g][j * 2]);
                    }
        }
        __syncthreads();   // stage may be re-filled by next-next issue
    }

    // ---- epilogue -------------------------------------------------------------
    const int gid = lane >> 2, tig = lane & 3;
#pragma unroll
    for (int mt = 0; mt < 2; mt++)
#pragma unroll
        for (int g = 0; g < 2; g++)
#pragma unroll
            for (int j = 0; j < 2; j++) {
                const int nf = g * 2 + j;
                const int col = col0 + wn * 32 + g * 16 + j * 8 + tig * 2;
                const float2 bv = *(const float2*)(bias + col);
#pragma unroll
                for (int rs = 0; rs < 2; rs++) {
                    const int row = row0 + wm * 32 + mt * 16 + gid + rs * 8;
                    float v0 = acc[mt][nf][rs * 2 + 0] + bv.x;
                    float v1 = acc[mt][nf][rs * 2 + 1] + bv.y;
                    if (MODE == 0) {
                        const int s = col >> 8;
                        if (s == 0) { v0 *= SCALE; v1 *= SCALE; }
                        __nv_bfloat16 h0 = __float2bfloat16(v0);
                        __nv_bfloat16 l0 = __float2bfloat16(v0 - __bfloat162float(h0));
                        __nv_bfloat16 h1 = __float2bfloat16(v1);
                        __nv_bfloat16 l1 = __float2bfloat16(v1 - __bfloat162float(h1));
                        const int hh = (col >> 5) & 7, d = col & 31;
                        const int b = row >> 6, n = row & 63;
                        const size_t pb = (size_t)(b * 8 + hh) * 2048;
                        if (s == 0) {
                            *(__nv_bfloat162*)(g_q_hi + pb + n * 32 + d) = __halves2bfloat162(h0, h1);
                            *(__nv_bfloat162*)(g_q_lo + pb + n * 32 + d) = __halves2bfloat162(l0, l1);
                        } else if (s == 1) {
                            *(__nv_bfloat162*)(g_k_hi + pb + n * 32 + d) = __halves2bfloat162(h0, h1);
                            *(__nv_bfloat162*)(g_k_lo + pb + n * 32 + d) = __halves2bfloat162(l0, l1);
                        } else {   // v, stored transposed [d][n]
                            g_vt_hi[pb + (size_t)d * 64 + n]       = h0;
                            g_vt_hi[pb + (size_t)(d + 1) * 64 + n] = h1;
                            g_vt_lo[pb + (size_t)d * 64 + n]       = l0;
                            g_vt_lo[pb + (size_t)(d + 1) * 64 + n] = l1;
                        }
                    } else {
                        *(float2*)(out + (size_t)row * 256 + col)
                            = make_float2(v0, v1);
                    }
                }
            }
}

// ================= HMMA attention: one (window, head) per CTA ===============
#define QSTR 40
#define VSTR 72

__global__ void __launch_bounds__(128)
attn_mma(const float* __restrict__ mask, const float* __restrict__ bias_table)
{
    const int bh = blockIdx.x;
    const int b  = bh >> 3;
    const int h  = bh & 7;

    __shared__ __nv_bfloat16 sQh[64 * QSTR], sQl[64 * QSTR];
    __shared__ __nv_bfloat16 sKh[64 * QSTR], sKl[64 * QSTR];
    __shared__ __nv_bfloat16 sVh[32 * VSTR], sVl[32 * VSTR];
    __shared__ float bt[228];

    const int tid  = threadIdx.x;
    const int warp = tid >> 5;
    const int lane = tid & 31;

    const __nv_bfloat16* Qh = g_q_hi  + (size_t)bh * 2048;
    const __nv_bfloat16* Ql = g_q_lo  + (size_t)bh * 2048;
    const __nv_bfloat16* Kh = g_k_hi  + (size_t)bh * 2048;
    const __nv_bfloat16* Kl = g_k_lo  + (size_t)bh * 2048;
    const __nv_bfloat16* Vh = g_vt_hi + (size_t)bh * 2048;
    const __nv_bfloat16* Vl = g_vt_lo + (size_t)bh * 2048;

    for (int c = tid; c < 256; c += 128) {
        const int qr = c >> 2, qc = (c & 3) * 8;
        *(uint4*)(sQh + qr * QSTR + qc) = *(const uint4*)(Qh + c * 8);
        *(uint4*)(sQl + qr * QSTR + qc) = *(const uint4*)(Ql + c * 8);
        *(uint4*)(sKh + qr * QSTR + qc) = *(const uint4*)(Kh + c * 8);
        *(uint4*)(sKl + qr * QSTR + qc) = *(const uint4*)(Kl + c * 8);
        const int vr = c >> 3, vc = (c & 7) * 8;
        *(uint4*)(sVh + vr * VSTR + vc) = *(const uint4*)(Vh + c * 8);
        *(uint4*)(sVl + vr * VSTR + vc) = *(const uint4*)(Vl + c * 8);
    }
    for (int t = tid; t < 225; t += 128) bt[t] = bias_table[t * NHEADS + h];
    __syncthreads();

    const int gid = lane >> 2, tig = lane & 3;
    const int a_rowoff = (warp * 16 + (lane & 15)) * QSTR + (lane >> 4) * 8;
    const int b_row    = ((lane >> 4) << 3) + (lane & 7);
    const int b_ksel   = ((lane >> 3) & 1) << 3;

    // ---- QK^T ----------------------------------------------------------------
    float acc[8][4];
#pragma unroll
    for (int nt = 0; nt < 8; nt++)
#pragma unroll
        for (int c = 0; c < 4; c++) acc[nt][c] = 0.f;

#pragma unroll
    for (int kt = 0; kt < 2; kt++) {
        uint32_t qh[4], ql[4];
        ldsm_x4(qh, smem_u32(sQh + a_rowoff + kt * 16));
        ldsm_x4(ql, smem_u32(sQl + a_rowoff + kt * 16));
#pragma unroll
        for (int ng = 0; ng < 4; ng++) {
            uint32_t kh[4], kl[4];
            const int off = (ng * 16 + b_row) * QSTR + kt * 16 + b_ksel;
            ldsm_x4(kh, smem_u32(sKh + off));
            ldsm_x4(kl, smem_u32(sKl + off));
#pragma unroll
            for (int j = 0; j < 2; j++) {
                float* c = acc[ng * 2 + j];
                mma16816(c, qh, &kh[j * 2]);
                mma16816(c, qh, &kl[j * 2]);
                mma16816(c, ql, &kh[j * 2]);
            }
        }
    }

    // ---- bias + mask ----------------------------------------------------------
    const int i0 = warp * 16 + gid, i1 = i0 + 8;
    const int yi0 = i0 >> 3, xi0 = i0 & 7;
    const int yi1 = i1 >> 3, xi1 = i1 & 7;
    const float* mrow = mask + (size_t)b * 4096;
#pragma unroll
    for (int nt = 0; nt < 8; nt++) {
        const int col = nt * 8 + tig * 2;
        const float2 m0 = *(const float2*)(mrow + i0 * 64 + col);
        const float2 m1 = *(const float2*)(mrow + i1 * 64 + col);
        acc[nt][0] += bt[(yi0 - nt + 7) * 15 + (xi0 - tig * 2 + 7)] + m0.x;
        acc[nt][1] += bt[(yi0 - nt + 7) * 15 + (xi0 - tig * 2 + 6)] + m0.y;
        acc[nt][2] += bt[(yi1 - nt + 7) * 15 + (xi1 - tig * 2 + 7)] + m1.x;
        acc[nt][3] += bt[(yi1 - nt + 7) * 15 + (xi1 - tig * 2 + 6)] + m1.y;
    }

    // ---- softmax ---------------------------------------------------------------
    float mx0 = -1e30f, mx1 = -1e30f;
#pragma unroll
    for (int nt = 0; nt < 8; nt++) {
        mx0 = fmaxf(mx0, fmaxf(acc[nt][0], acc[nt][1]));
        mx1 = fmaxf(mx1, fmaxf(acc[nt][2], acc[nt][3]));
    }
    mx0 = fmaxf(mx0, __shfl_xor_sync(0xffffffffu, mx0, 1));
    mx0 = fmaxf(mx0, __shfl_xor_sync(0xffffffffu, mx0, 2));
    mx1 = fmaxf(mx1, __shfl_xor_sync(0xffffffffu, mx1, 1));
    mx1 = fmaxf(mx1, __shfl_xor_sync(0xffffffffu, mx1, 2));

    float sum0 = 0.f, sum1 = 0.f;
#pragma unroll
    for (int nt = 0; nt < 8; nt++) {
        acc[nt][0] = __expf(acc[nt][0] - mx0);
        acc[nt][1] = __expf(acc[nt][1] - mx0);
        acc[nt][2] = __expf(acc[nt][2] - mx1);
        acc[nt][3] = __expf(acc[nt][3] - mx1);
        sum0 += acc[nt][0] + acc[nt][1];
        sum1 += acc[nt][2] + acc[nt][3];
    }
    sum0 += __shfl_xor_sync(0xffffffffu, sum0, 1);
    sum0 += __shfl_xor_sync(0xffffffffu, sum0, 2);
    sum1 += __shfl_xor_sync(0xffffffffu, sum1, 1);
    sum1 += __shfl_xor_sync(0xffffffffu, sum1, 2);
    const float inv0 = 1.f / sum0, inv1 = 1.f / sum1;

    // ---- repack P into A-fragments (hi/lo split) --------------------------------
    uint32_t phi[4][4], plo[4][4];
#pragma unroll
    for (int kt = 0; kt < 4; kt++) {
        const float f[4][2] = {
            {acc[kt*2][0] * inv0,   acc[kt*2][1] * inv0},
            {acc[kt*2][2] * inv1,   acc[kt*2][3] * inv1},
            {acc[kt*2+1][0] * inv0, acc[kt*2+1][1] * inv0},
            {acc[kt*2+1][2] * inv1, acc[kt*2+1][3] * inv1}};
#pragma unroll
        for (int r = 0; r < 4; r++) {
            __nv_bfloat16 hx = __float2bfloat16(f[r][0]);
            __nv_bfloat16 hy = __float2bfloat16(f[r][1]);
            phi[kt][r] = pack_bf16x2(f[r][0], f[r][1]);
            plo[kt][r] = pack_bf16x2(f[r][0] - __bfloat162float(hx),
                                     f[r][1] - __bfloat162float(hy));
        }
    }

    // ---- P * V -------------------------------------------------------------------
    float ao[4][4];
#pragma unroll
    for (int dn = 0; dn < 4; dn++)
#pragma unroll
        for (int c = 0; c < 4; c++) ao[dn][c] = 0.f;

#pragma unroll
    for (int kt = 0; kt < 4; kt++) {
#pragma unroll
        for (int g = 0; g < 2; g++) {
            uint32_t vh[4], vl[4];
            const int off = (g * 16 + b_row) * VSTR + kt * 16 + b_ksel;
            ldsm_x4(vh, smem_u32(sVh + off));
            ldsm_x4(vl, smem_u32(sVl + off));
#pragma unroll
            for (int j = 0; j < 2; j++) {
                float* c = ao[g * 2 + j];
                mma16816(c, phi[kt], &vh[j * 2]);
                mma16816(c, phi[kt], &vl[j * 2]);
                mma16816(c, plo[kt], &vh[j * 2]);
            }
        }
    }

    // ---- epilogue --------------------------------------------------------------
#pragma unroll
    for (int dn = 0; dn < 4; dn++) {
        const int d = dn * 8 + tig * 2;
#pragma unroll
        for (int rs = 0; rs < 2; rs++) {
            const int row = rs ? i1 : i0;
            const float v0 = ao[dn][rs * 2 + 0];
            const float v1 = ao[dn][rs * 2 + 1];
            __nv_bfloat16 h0 = __float2bfloat16(v0);
            __nv_bfloat16 l0 = __float2bfloat16(v0 - __bfloat162float(h0));
            __nv_bfloat16 h1 = __float2bfloat16(v1);
            __nv_bfloat16 l1 = __float2bfloat16(v1 - __bfloat162float(h1));
            const size_t o = ((size_t)b * 64 + row) * DIM + h * 32 + d;
            *(__nv_bfloat162*)(g_ao_hi + o) = __halves2bfloat162(h0, h1);
            *(__nv_bfloat162*)(g_ao_lo + o) = __halves2bfloat162(l0, l1);
        }
    }
}

// ---------------- launch ----------------------------------------------------
extern "C" void kernel_launch(void* const* d_in, const int* in_sizes, int n_in,
                              void* d_out, int out_size)
{
    const float* x          = (const float*)d_in[0]; // (2048,64,256)
    const float* mask       = (const float*)d_in[1]; // (2048,1,64,64)
    const float* w_qkv      = (const float*)d_in[2]; // (768,256)
    const float* b_qkv      = (const float*)d_in[3]; // (768)
    const float* w_proj     = (const float*)d_in[4]; // (256,256)
    const float* b_proj     = (const float*)d_in[5]; // (256)
    const float* bias_table = (const float*)d_in[6]; // (225,8)
    float* out = (float*)d_out;                      // (2048,64,256)

    (void)in_sizes; (void)n_in; (void)out_size;

    __nv_bfloat16 *xh, *xl, *wqh, *wql, *wph, *wpl, *aoh, *aol;
    cudaGetSymbolAddress((void**)&xh,  g_x_hi);
    cudaGetSymbolAddress((void**)&xl,  g_x_lo);
    cudaGetSymbolAddress((void**)&wqh, g_wq_hi);
    cudaGetSymbolAddress((void**)&wql, g_wq_lo);
    cudaGetSymbolAddress((void**)&wph, g_wp_hi);
    cudaGetSymbolAddress((void**)&wpl, g_wp_lo);
    cudaGetSymbolAddress((void**)&aoh, g_ao_hi);
    cudaGetSymbolAddress((void**)&aol, g_ao_lo);

    cudaFuncSetAttribute(gemm_mma<0>, cudaFuncAttributeMaxDynamicSharedMemorySize, GEMM_SMEM);
    cudaFuncSetAttribute(gemm_mma<1>, cudaFuncAttributeMaxDynamicSharedMemorySize, GEMM_SMEM);

    // 0) fp32 -> bf16 hi/lo splits
    {
        int n4 = (MROWS * DIM) / 4;
        convert_split<<<(n4 + 255) / 256, 256>>>(x, xh, xl, n4);
        int w4 = (QKVDIM * DIM) / 4;
        convert_split<<<(w4 + 255) / 256, 256>>>(w_qkv, wqh, wql, w4);
        int p4 = (DIM * DIM) / 4;
        convert_split<<<(p4 + 255) / 256, 256>>>(w_proj, wph, wpl, p4);
    }
    // 1) QKV GEMM (HMMA, cp.async) -> q/k/vt bf16 hi/lo planes (q pre-scaled)
    {
        dim3 grid(QKVDIM / 64, MROWS / 128);   // 12 x 1024
        gemm_mma<0><<<grid, 256, GEMM_SMEM>>>(xh, xl, wqh, wql, b_qkv, nullptr);
    }
    // 2) windowed attention (HMMA) -> g_ao hi/lo
    attn_mma<<<B_WIN * NHEADS, 128>>>(mask, bias_table);
    // 3) output projection (HMMA, cp.async) -> out
    {
        dim3 grid(DIM / 64, MROWS / 128);      // 4 x 1024
        gemm_mma<1><<<grid, 256, GEMM_SMEM>>>(aoh, aol, wph, wpl, b_proj, out);
    }
}

// round 7
// speedup vs baseline: 3.0888x; 1.0110x over previous
#include <cuda_runtime.h>
#include <cuda_bf16.h>
#include <cstdint>

#define B_WIN   2048
#define NTOK    64
#define DIM     256
#define NHEADS  8
#define QKVDIM  768
#define MROWS   (B_WIN * NTOK)          // 131072
#define SCALE   0.17677669529663687f    // 32^-0.5

// ---------------- scratch (device globals; no cudaMalloc allowed) ----------
#define HEAD_ELEMS (2048ull * 8ull * 64ull * 32ull)   // 33.5M per plane
__device__ __nv_bfloat16 g_q_hi[HEAD_ELEMS],  g_q_lo[HEAD_ELEMS];
__device__ __nv_bfloat16 g_k_hi[HEAD_ELEMS],  g_k_lo[HEAD_ELEMS];
__device__ __nv_bfloat16 g_vt_hi[HEAD_ELEMS], g_vt_lo[HEAD_ELEMS];  // [bh][d][n]
__device__ __nv_bfloat16 g_x_hi[(size_t)MROWS * DIM];
__device__ __nv_bfloat16 g_x_lo[(size_t)MROWS * DIM];
__device__ __nv_bfloat16 g_ao_hi[(size_t)MROWS * DIM];
__device__ __nv_bfloat16 g_ao_lo[(size_t)MROWS * DIM];
__device__ __nv_bfloat16 g_wq_hi[QKVDIM * DIM];
__device__ __nv_bfloat16 g_wq_lo[QKVDIM * DIM];
__device__ __nv_bfloat16 g_wp_hi[DIM * DIM];
__device__ __nv_bfloat16 g_wp_lo[DIM * DIM];

// ================= helpers ==================================================
__device__ __forceinline__ uint32_t smem_u32(const void* p) {
    uint32_t a;
    asm("{ .reg .u64 t; cvta.to.shared.u64 t, %1; cvt.u32.u64 %0, t; }"
        : "=r"(a) : "l"(p));
    return a;
}

__device__ __forceinline__ void ldsm_x4(uint32_t* r, uint32_t addr) {
    asm volatile("ldmatrix.sync.aligned.m8n8.x4.shared.b16 {%0,%1,%2,%3}, [%4];"
                 : "=r"(r[0]), "=r"(r[1]), "=r"(r[2]), "=r"(r[3]) : "r"(addr));
}

// D += A(bf16 16x16) * B(bf16 16x8), fp32 accumulate
__device__ __forceinline__ void mma16816(float* c, const uint32_t* a, const uint32_t* b) {
    asm volatile("mma.sync.aligned.m16n8k16.row.col.f32.bf16.bf16.f32 "
                 "{%0,%1,%2,%3}, {%4,%5,%6,%7}, {%8,%9}, {%0,%1,%2,%3};"
                 : "+f"(c[0]), "+f"(c[1]), "+f"(c[2]), "+f"(c[3])
                 : "r"(a[0]), "r"(a[1]), "r"(a[2]), "r"(a[3]),
                   "r"(b[0]), "r"(b[1]));
}

__device__ __forceinline__ uint32_t pack_bf16x2(float x, float y) {
    __nv_bfloat162 t = __floats2bfloat162_rn(x, y);
    return *(uint32_t*)&t;
}

__device__ __forceinline__ void cp16(uint32_t dst, const void* src) {
    asm volatile("cp.async.cg.shared.global [%0], [%1], 16;"
                 :: "r"(dst), "l"(src) : "memory");
}
#define CP_COMMIT() asm volatile("cp.async.commit_group;" ::: "memory")

// ================= fp32 -> (hi, lo) bf16 split =============================
__global__ void convert_split(const float* __restrict__ src,
                              __nv_bfloat16* __restrict__ hi,
                              __nv_bfloat16* __restrict__ lo, int n4)
{
    int i = blockIdx.x * blockDim.x + threadIdx.x;
    if (i >= n4) return;
    float4 v = ((const float4*)src)[i];
    float f[4] = {v.x, v.y, v.z, v.w};
    __nv_bfloat16 h[4], l[4];
#pragma unroll
    for (int k = 0; k < 4; k++) {
        h[k] = __float2bfloat16(f[k]);
        l[k] = __float2bfloat16(f[k] - __bfloat162float(h[k]));
    }
    ((__nv_bfloat162*)hi)[2*i]   = __halves2bfloat162(h[0], h[1]);
    ((__nv_bfloat162*)hi)[2*i+1] = __halves2bfloat162(h[2], h[3]);
    ((__nv_bfloat162*)lo)[2*i]   = __halves2bfloat162(l[0], l[1]);
    ((__nv_bfloat162*)lo)[2*i+1] = __halves2bfloat162(l[2], l[3]);
}

// ================= HMMA GEMM (cp.async, 128x128 block, warp tile 32x64) ====
// C[128 x 128] = A[128 x 256] * W[128 x 256]^T  (3-term bf16 split)
// 8 warps: 4(M) x 2(N), warp tile 32x64, BK=32, 2 async stages.
// MODE 0: epilogue splits into q/k/vt bf16 hi/lo planes (q scaled).
// MODE 1: writes fp32 `out`.

#define SROWB   80                  // bytes per smem row (40 bf16, conflict-free)
#define OFF_AH  0
#define OFF_AL  10240
#define OFF_BH  20480
#define OFF_BL  30720
#define STAGE   40960
#define GEMM_SMEM (2 * STAGE)       // 81920 bytes

template <int MODE>
__global__ void __launch_bounds__(256, 2)
gemm_mma(const __nv_bfloat16* __restrict__ Ah, const __nv_bfloat16* __restrict__ Al,
         const __nv_bfloat16* __restrict__ Wh, const __nv_bfloat16* __restrict__ Wl,
         const float* __restrict__ bias, float* __restrict__ out)
{
    extern __shared__ char smem[];
    const uint32_t sb = smem_u32(smem);

    const int tid  = threadIdx.x;
    const int lane = tid & 31;
    const int warp = tid >> 5;
    const int wm   = warp >> 1;          // 0..3
    const int wn   = warp & 1;           // 0..1
    const int row0 = blockIdx.y * 128;
    const int col0 = blockIdx.x * 128;

    float acc[2][8][4];
#pragma unroll
    for (int a = 0; a < 2; a++)
#pragma unroll
        for (int b = 0; b < 8; b++)
#pragma unroll
            for (int c = 0; c < 4; c++) acc[a][b][c] = 0.f;

    // load geometry: 512 16B-chunks per plane per stage (128 rows x 4 chunks)
    const int lrow = tid >> 2;            // c = tid + t*256 -> row = c>>2 (t adds 64)
    const int lc4  = (tid & 3);
    const uint32_t so_base = (uint32_t)lrow * SROWB + lc4 * 16;

    // ldmatrix lane addressing (element offsets)
    const int a_row  = wm * 32 + (lane & 15);
    const int a_ksel = (lane >> 4) * 8;
    const int b_rowb = wn * 64 + ((lane >> 4) << 3) + (lane & 7);
    const int b_ksel = ((lane >> 3) & 1) << 3;

    auto issue = [&](int kc, uint32_t stb) {
        const int k0 = kc * 32;
#pragma unroll
        for (int t = 0; t < 2; t++) {
            const int r = lrow + t * 64;
            const uint32_t so = so_base + t * 64 * SROWB;
            const size_t ga = (size_t)(row0 + r) * 256 + k0 + lc4 * 8;
            const size_t gb = (size_t)(col0 + r) * 256 + k0 + lc4 * 8;
            cp16(stb + OFF_AH + so, Ah + ga);
            cp16(stb + OFF_AL + so, Al + ga);
            cp16(stb + OFF_BH + so, Wh + gb);
            cp16(stb + OFF_BL + so, Wl + gb);
        }
    };

    issue(0, sb);
    CP_COMMIT();

    for (int kc = 0; kc < 8; kc++) {
        if (kc < 7) {
            issue(kc + 1, sb + ((kc + 1) & 1) * STAGE);
            CP_COMMIT();
            asm volatile("cp.async.wait_group 1;" ::: "memory");
        } else {
            asm volatile("cp.async.wait_group 0;" ::: "memory");
        }
        __syncthreads();

        const uint32_t stb = sb + (kc & 1) * STAGE;
#pragma unroll
        for (int kk = 0; kk < 32; kk += 16) {
            uint32_t a_h[2][4], a_l[2][4];
#pragma unroll
            for (int mt = 0; mt < 2; mt++) {
                const uint32_t off = (uint32_t)(a_row + mt * 16) * SROWB
                                   + (kk + a_ksel) * 2;
                ldsm_x4(a_h[mt], stb + OFF_AH + off);
                ldsm_x4(a_l[mt], stb + OFF_AL + off);
            }
#pragma unroll
            for (int g = 0; g < 4; g++) {
                uint32_t b_h[4], b_l[4];
                const uint32_t off = (uint32_t)(b_rowb + g * 16) * SROWB
                                   + (kk + b_ksel) * 2;
                ldsm_x4(b_h, stb + OFF_BH + off);
                ldsm_x4(b_l, stb + OFF_BL + off);
#pragma unroll
                for (int mt = 0; mt < 2; mt++)
#pragma unroll
                    for (int j = 0; j < 2; j++) {
                        float* c = acc[mt][g * 2 + j];
                        mma16816(c, a_h[mt], &b_h[j * 2]);
                        mma16816(c, a_h[mt], &b_l[j * 2]);
                        mma16816(c, a_l[mt], &b_h[j * 2]);
                    }
            }
        }
        __syncthreads();
    }

    // ---- epilogue -------------------------------------------------------------
    const int gid = lane >> 2, tig = lane & 3;
#pragma unroll
    for (int mt = 0; mt < 2; mt++)
#pragma unroll
        for (int g = 0; g < 4; g++)
#pragma unroll
            for (int j = 0; j < 2; j++) {
                const int nf = g * 2 + j;
                const int col = col0 + wn * 64 + g * 16 + j * 8 + tig * 2;
                const float2 bv = *(const float2*)(bias + col);
#pragma unroll
                for (int rs = 0; rs < 2; rs++) {
                    const int row = row0 + wm * 32 + mt * 16 + gid + rs * 8;
                    float v0 = acc[mt][nf][rs * 2 + 0] + bv.x;
                    float v1 = acc[mt][nf][rs * 2 + 1] + bv.y;
                    if (MODE == 0) {
                        const int s = col >> 8;
                        if (s == 0) { v0 *= SCALE; v1 *= SCALE; }
                        __nv_bfloat16 h0 = __float2bfloat16(v0);
                        __nv_bfloat16 l0 = __float2bfloat16(v0 - __bfloat162float(h0));
                        __nv_bfloat16 h1 = __float2bfloat16(v1);
                        __nv_bfloat16 l1 = __float2bfloat16(v1 - __bfloat162float(h1));
                        const int hh = (col >> 5) & 7, d = col & 31;
                        const int b = row >> 6, n = row & 63;
                        const size_t pb = (size_t)(b * 8 + hh) * 2048;
                        if (s == 0) {
                            *(__nv_bfloat162*)(g_q_hi + pb + n * 32 + d) = __halves2bfloat162(h0, h1);
                            *(__nv_bfloat162*)(g_q_lo + pb + n * 32 + d) = __halves2bfloat162(l0, l1);
                        } else if (s == 1) {
                            *(__nv_bfloat162*)(g_k_hi + pb + n * 32 + d) = __halves2bfloat162(h0, h1);
                            *(__nv_bfloat162*)(g_k_lo + pb + n * 32 + d) = __halves2bfloat162(l0, l1);
                        } else {   // v, stored transposed [d][n]
                            g_vt_hi[pb + (size_t)d * 64 + n]       = h0;
                            g_vt_hi[pb + (size_t)(d + 1) * 64 + n] = h1;
                            g_vt_lo[pb + (size_t)d * 64 + n]       = l0;
                            g_vt_lo[pb + (size_t)(d + 1) * 64 + n] = l1;
                        }
                    } else {
                        *(float2*)(out + (size_t)row * 256 + col)
                            = make_float2(v0, v1);
                    }
                }
            }
}

// ================= HMMA attention: one (window, head) per CTA ===============
#define QSTR 40
#define VSTR 72

__global__ void __launch_bounds__(128)
attn_mma(const float* __restrict__ mask, const float* __restrict__ bias_table)
{
    const int bh = blockIdx.x;
    const int b  = bh >> 3;
    const int h  = bh & 7;

    __shared__ __nv_bfloat16 sQh[64 * QSTR], sQl[64 * QSTR];
    __shared__ __nv_bfloat16 sKh[64 * QSTR], sKl[64 * QSTR];
    __shared__ __nv_bfloat16 sVh[32 * VSTR], sVl[32 * VSTR];
    __shared__ float bt[228];

    const int tid  = threadIdx.x;
    const int warp = tid >> 5;
    const int lane = tid & 31;

    const __nv_bfloat16* Qh = g_q_hi  + (size_t)bh * 2048;
    const __nv_bfloat16* Ql = g_q_lo  + (size_t)bh * 2048;
    const __nv_bfloat16* Kh = g_k_hi  + (size_t)bh * 2048;
    const __nv_bfloat16* Kl = g_k_lo  + (size_t)bh * 2048;
    const __nv_bfloat16* Vh = g_vt_hi + (size_t)bh * 2048;
    const __nv_bfloat16* Vl = g_vt_lo + (size_t)bh * 2048;

    for (int c = tid; c < 256; c += 128) {
        const int qr = c >> 2, qc = (c & 3) * 8;
        *(uint4*)(sQh + qr * QSTR + qc) = *(const uint4*)(Qh + c * 8);
        *(uint4*)(sQl + qr * QSTR + qc) = *(const uint4*)(Ql + c * 8);
        *(uint4*)(sKh + qr * QSTR + qc) = *(const uint4*)(Kh + c * 8);
        *(uint4*)(sKl + qr * QSTR + qc) = *(const uint4*)(Kl + c * 8);
        const int vr = c >> 3, vc = (c & 7) * 8;
        *(uint4*)(sVh + vr * VSTR + vc) = *(const uint4*)(Vh + c * 8);
        *(uint4*)(sVl + vr * VSTR + vc) = *(const uint4*)(Vl + c * 8);
    }
    for (int t = tid; t < 225; t += 128) bt[t] = bias_table[t * NHEADS + h];
    __syncthreads();

    const int gid = lane >> 2, tig = lane & 3;
    const int a_rowoff = (warp * 16 + (lane & 15)) * QSTR + (lane >> 4) * 8;
    const int b_row    = ((lane >> 4) << 3) + (lane & 7);
    const int b_ksel   = ((lane >> 3) & 1) << 3;

    // ---- QK^T ----------------------------------------------------------------
    float acc[8][4];
#pragma unroll
    for (int nt = 0; nt < 8; nt++)
#pragma unroll
        for (int c = 0; c < 4; c++) acc[nt][c] = 0.f;

#pragma unroll
    for (int kt = 0; kt < 2; kt++) {
        uint32_t qh[4], ql[4];
        ldsm_x4(qh, smem_u32(sQh + a_rowoff + kt * 16));
        ldsm_x4(ql, smem_u32(sQl + a_rowoff + kt * 16));
#pragma unroll
        for (int ng = 0; ng < 4; ng++) {
            uint32_t kh[4], kl[4];
            const int off = (ng * 16 + b_row) * QSTR + kt * 16 + b_ksel;
            ldsm_x4(kh, smem_u32(sKh + off));
            ldsm_x4(kl, smem_u32(sKl + off));
#pragma unroll
            for (int j = 0; j < 2; j++) {
                float* c = acc[ng * 2 + j];
                mma16816(c, qh, &kh[j * 2]);
                mma16816(c, qh, &kl[j * 2]);
                mma16816(c, ql, &kh[j * 2]);
            }
        }
    }

    // ---- bias + mask ----------------------------------------------------------
    const int i0 = warp * 16 + gid, i1 = i0 + 8;
    const int yi0 = i0 >> 3, xi0 = i0 & 7;
    const int yi1 = i1 >> 3, xi1 = i1 & 7;
    const float* mrow = mask + (size_t)b * 4096;
#pragma unroll
    for (int nt = 0; nt < 8; nt++) {
        const int col = nt * 8 + tig * 2;
        const float2 m0 = *(const float2*)(mrow + i0 * 64 + col);
        const float2 m1 = *(const float2*)(mrow + i1 * 64 + col);
        acc[nt][0] += bt[(yi0 - nt + 7) * 15 + (xi0 - tig * 2 + 7)] + m0.x;
        acc[nt][1] += bt[(yi0 - nt + 7) * 15 + (xi0 - tig * 2 + 6)] + m0.y;
        acc[nt][2] += bt[(yi1 - nt + 7) * 15 + (xi1 - tig * 2 + 7)] + m1.x;
        acc[nt][3] += bt[(yi1 - nt + 7) * 15 + (xi1 - tig * 2 + 6)] + m1.y;
    }

    // ---- softmax ---------------------------------------------------------------
    float mx0 = -1e30f, mx1 = -1e30f;
#pragma unroll
    for (int nt = 0; nt < 8; nt++) {
        mx0 = fmaxf(mx0, fmaxf(acc[nt][0], acc[nt][1]));
        mx1 = fmaxf(mx1, fmaxf(acc[nt][2], acc[nt][3]));
    }
    mx0 = fmaxf(mx0, __shfl_xor_sync(0xffffffffu, mx0, 1));
    mx0 = fmaxf(mx0, __shfl_xor_sync(0xffffffffu, mx0, 2));
    mx1 = fmaxf(mx1, __shfl_xor_sync(0xffffffffu, mx1, 1));
    mx1 = fmaxf(mx1, __shfl_xor_sync(0xffffffffu, mx1, 2));

    float sum0 = 0.f, sum1 = 0.f;
#pragma unroll
    for (int nt = 0; nt < 8; nt++) {
        acc[nt][0] = __expf(acc[nt][0] - mx0);
        acc[nt][1] = __expf(acc[nt][1] - mx0);
        acc[nt][2] = __expf(acc[nt][2] - mx1);
        acc[nt][3] = __expf(acc[nt][3] - mx1);
        sum0 += acc[nt][0] + acc[nt][1];
        sum1 += acc[nt][2] + acc[nt][3];
    }
    sum0 += __shfl_xor_sync(0xffffffffu, sum0, 1);
    sum0 += __shfl_xor_sync(0xffffffffu, sum0, 2);
    sum1 += __shfl_xor_sync(0xffffffffu, sum1, 1);
    sum1 += __shfl_xor_sync(0xffffffffu, sum1, 2);
    const float inv0 = 1.f / sum0, inv1 = 1.f / sum1;

    // ---- repack P into A-fragments (hi/lo split) --------------------------------
    uint32_t phi[4][4], plo[4][4];
#pragma unroll
    for (int kt = 0; kt < 4; kt++) {
        const float f[4][2] = {
            {acc[kt*2][0] * inv0,   acc[kt*2][1] * inv0},
            {acc[kt*2][2] * inv1,   acc[kt*2][3] * inv1},
            {acc[kt*2+1][0] * inv0, acc[kt*2+1][1] * inv0},
            {acc[kt*2+1][2] * inv1, acc[kt*2+1][3] * inv1}};
#pragma unroll
        for (int r = 0; r < 4; r++) {
            __nv_bfloat16 hx = __float2bfloat16(f[r][0]);
            __nv_bfloat16 hy = __float2bfloat16(f[r][1]);
            phi[kt][r] = pack_bf16x2(f[r][0], f[r][1]);
            plo[kt][r] = pack_bf16x2(f[r][0] - __bfloat162float(hx),
                                     f[r][1] - __bfloat162float(hy));
        }
    }

    // ---- P * V -------------------------------------------------------------------
    float ao[4][4];
#pragma unroll
    for (int dn = 0; dn < 4; dn++)
#pragma unroll
        for (int c = 0; c < 4; c++) ao[dn][c] = 0.f;

#pragma unroll
    for (int kt = 0; kt < 4; kt++) {
#pragma unroll
        for (int g = 0; g < 2; g++) {
            uint32_t vh[4], vl[4];
            const int off = (g * 16 + b_row) * VSTR + kt * 16 + b_ksel;
            ldsm_x4(vh, smem_u32(sVh + off));
            ldsm_x4(vl, smem_u32(sVl + off));
#pragma unroll
            for (int j = 0; j < 2; j++) {
                float* c = ao[g * 2 + j];
                mma16816(c, phi[kt], &vh[j * 2]);
                mma16816(c, phi[kt], &vl[j * 2]);
                mma16816(c, plo[kt], &vh[j * 2]);
            }
        }
    }

    // ---- epilogue --------------------------------------------------------------
#pragma unroll
    for (int dn = 0; dn < 4; dn++) {
        const int d = dn * 8 + tig * 2;
#pragma unroll
        for (int rs = 0; rs < 2; rs++) {
            const int row = rs ? i1 : i0;
            const float v0 = ao[dn][rs * 2 + 0];
            const float v1 = ao[dn][rs * 2 + 1];
            __nv_bfloat16 h0 = __float2bfloat16(v0);
            __nv_bfloat16 l0 = __float2bfloat16(v0 - __bfloat162float(h0));
            __nv_bfloat16 h1 = __float2bfloat16(v1);
            __nv_bfloat16 l1 = __float2bfloat16(v1 - __bfloat162float(h1));
            const size_t o = ((size_t)b * 64 + row) * DIM + h * 32 + d;
            *(__nv_bfloat162*)(g_ao_hi + o) = __halves2bfloat162(h0, h1);
            *(__nv_bfloat162*)(g_ao_lo + o) = __halves2bfloat162(l0, l1);
        }
    }
}

// ---------------- launch ----------------------------------------------------
extern "C" void kernel_launch(void* const* d_in, const int* in_sizes, int n_in,
                              void* d_out, int out_size)
{
    const float* x          = (const float*)d_in[0]; // (2048,64,256)
    const float* mask       = (const float*)d_in[1]; // (2048,1,64,64)
    const float* w_qkv      = (const float*)d_in[2]; // (768,256)
    const float* b_qkv      = (const float*)d_in[3]; // (768)
    const float* w_proj     = (const float*)d_in[4]; // (256,256)
    const float* b_proj     = (const float*)d_in[5]; // (256)
    const float* bias_table = (const float*)d_in[6]; // (225,8)
    float* out = (float*)d_out;                      // (2048,64,256)

    (void)in_sizes; (void)n_in; (void)out_size;

    __nv_bfloat16 *xh, *xl, *wqh, *wql, *wph, *wpl, *aoh, *aol;
    cudaGetSymbolAddress((void**)&xh,  g_x_hi);
    cudaGetSymbolAddress((void**)&xl,  g_x_lo);
    cudaGetSymbolAddress((void**)&wqh, g_wq_hi);
    cudaGetSymbolAddress((void**)&wql, g_wq_lo);
    cudaGetSymbolAddress((void**)&wph, g_wp_hi);
    cudaGetSymbolAddress((void**)&wpl, g_wp_lo);
    cudaGetSymbolAddress((void**)&aoh, g_ao_hi);
    cudaGetSymbolAddress((void**)&aol, g_ao_lo);

    cudaFuncSetAttribute(gemm_mma<0>, cudaFuncAttributeMaxDynamicSharedMemorySize, GEMM_SMEM);
    cudaFuncSetAttribute(gemm_mma<1>, cudaFuncAttributeMaxDynamicSharedMemorySize, GEMM_SMEM);

    // 0) fp32 -> bf16 hi/lo splits
    {
        int n4 = (MROWS * DIM) / 4;
        convert_split<<<(n4 + 255) / 256, 256>>>(x, xh, xl, n4);
        int w4 = (QKVDIM * DIM) / 4;
        convert_split<<<(w4 + 255) / 256, 256>>>(w_qkv, wqh, wql, w4);
        int p4 = (DIM * DIM) / 4;
        convert_split<<<(p4 + 255) / 256, 256>>>(w_proj, wph, wpl, p4);
    }
    // 1) QKV GEMM (HMMA, cp.async) -> q/k/vt bf16 hi/lo planes (q pre-scaled)
    {
        dim3 grid(QKVDIM / 128, MROWS / 128);   // 6 x 1024
        gemm_mma<0><<<grid, 256, GEMM_SMEM>>>(xh, xl, wqh, wql, b_qkv, nullptr);
    }
    // 2) windowed attention (HMMA) -> g_ao hi/lo
    attn_mma<<<B_WIN * NHEADS, 128>>>(mask, bias_table);
    // 3) output projection (HMMA, cp.async) -> out
    {
        dim3 grid(DIM / 128, MROWS / 128);      // 2 x 1024
        gemm_mma<1><<<grid, 256, GEMM_SMEM>>>(aoh, aol, wph, wpl, b_proj, out);
    }
}